// round 3
// baseline (speedup 1.0000x reference)
#include <cuda_runtime.h>

#define BATCH   16384
#define SEQ_L   64
#define T_STEPS 32
#define NH      128

typedef unsigned long long u64;

// ---------------- packed fp32x2 helpers (sm_100+) ----------------
__device__ __forceinline__ u64 pack2(float x, float y) {
    u64 r; asm("mov.b64 %0,{%1,%2};" : "=l"(r) : "f"(x), "f"(y)); return r;
}
__device__ __forceinline__ u64 dup2(float x) { return pack2(x, x); }
__device__ __forceinline__ void unpack2(u64 v, float& x, float& y) {
    asm("mov.b64 {%0,%1},%2;" : "=f"(x), "=f"(y) : "l"(v));
}
__device__ __forceinline__ u64 fma2(u64 a, u64 b, u64 c) {
    u64 d; asm("fma.rn.f32x2 %0,%1,%2,%3;" : "=l"(d) : "l"(a), "l"(b), "l"(c)); return d;
}

__device__ __forceinline__ float sigf(float x) {
    return __fdividef(1.0f, 1.0f + __expf(-x));
}
__device__ __forceinline__ float tanhfast(float x) {
    return 1.0f - 2.0f * __fdividef(1.0f, __expf(2.0f * x) + 1.0f);
}

// hidden-state scratch: [B][T][NH] fp32 = 256 MB (static device array, no runtime alloc)
__device__ float g_hs[(size_t)BATCH * T_STEPS * NH];

// ============================================================================
// Kernel 1: GRU recurrence. 16 samples/CTA, 128 threads.
// smem: W_hh k-major [128][384] (192KB), h [16][128], input bits [32][16].
// Thread: c = tid&63 owns j-pair {2c,2c+1}; half = tid>>6 owns 8 samples.
// ============================================================================
__global__ __launch_bounds__(128, 1) void gru_kernel(
    const float* __restrict__ x, const float* __restrict__ w_ih,
    const float* __restrict__ w_hh, const float* __restrict__ b_ih,
    const float* __restrict__ b_hh)
{
    extern __shared__ float sm[];
    float* sW = sm;                                   // [k=128][gj=384]
    float* sH = sW + 128 * 384;                       // [16][128]
    unsigned char* sD = (unsigned char*)(sH + 16 * 128);  // [32][16]

    const int tid = threadIdx.x;
    const int c = tid & 63, half = tid >> 6;
    const int bBase = blockIdx.x * 16;
    const int j0 = 2 * c;

    // Stage W_hh transposed to k-major
    for (int i = tid; i < 384 * 128; i += 128) {
        int gj = i >> 7, k = i & 127;
        sW[k * 384 + gj] = w_hh[i];
    }
    // Teacher-forced input bits: data[t] = patches[t-1] (zeros at t=0)
    for (int i = tid; i < 32 * 16; i += 128) {
        int t = i >> 4, s = i & 15;
        unsigned char bits = 0;
        if (t > 0) {
            const float* xb = x + (size_t)(bBase + s) * SEQ_L + 2 * (t - 1);
            bits = (unsigned char)((xb[0] != 0.0f ? 1 : 0) | (xb[1] != 0.0f ? 2 : 0));
        }
        sD[i] = bits;
    }
    for (int i = tid; i < 16 * 128; i += 128) sH[i] = 0.0f;

    // Per-thread input-side params for its j-pair (gates r=0,z=1,n=2)
    u64 wiR0 = pack2(w_ih[(0 * 128 + j0) * 2 + 0], w_ih[(0 * 128 + j0 + 1) * 2 + 0]);
    u64 wiR1 = pack2(w_ih[(0 * 128 + j0) * 2 + 1], w_ih[(0 * 128 + j0 + 1) * 2 + 1]);
    u64 wiZ0 = pack2(w_ih[(1 * 128 + j0) * 2 + 0], w_ih[(1 * 128 + j0 + 1) * 2 + 0]);
    u64 wiZ1 = pack2(w_ih[(1 * 128 + j0) * 2 + 1], w_ih[(1 * 128 + j0 + 1) * 2 + 1]);
    u64 wiN0 = pack2(w_ih[(2 * 128 + j0) * 2 + 0], w_ih[(2 * 128 + j0 + 1) * 2 + 0]);
    u64 wiN1 = pack2(w_ih[(2 * 128 + j0) * 2 + 1], w_ih[(2 * 128 + j0 + 1) * 2 + 1]);
    u64 baseR = pack2(b_ih[j0] + b_hh[j0], b_ih[j0 + 1] + b_hh[j0 + 1]);
    u64 baseZ = pack2(b_ih[128 + j0] + b_hh[128 + j0], b_ih[128 + j0 + 1] + b_hh[128 + j0 + 1]);
    u64 binN  = pack2(b_ih[256 + j0], b_ih[256 + j0 + 1]);
    u64 bhnN  = pack2(b_hh[256 + j0], b_hh[256 + j0 + 1]);

    u64 hprev[8];
    #pragma unroll
    for (int s = 0; s < 8; s++) hprev[s] = 0ULL;

    __syncthreads();

    for (int t = 0; t < T_STEPS; t++) {
        u64 aR[8], aZ[8], aN[8], gN[8];
        #pragma unroll
        for (int s = 0; s < 8; s++) {
            unsigned char bits = sD[t * 16 + half * 8 + s];
            u64 d0 = dup2((bits & 1) ? 1.0f : 0.0f);
            u64 d1 = dup2((bits & 2) ? 1.0f : 0.0f);
            aR[s] = fma2(d0, wiR0, fma2(d1, wiR1, baseR));
            aZ[s] = fma2(d0, wiZ0, fma2(d1, wiZ1, baseZ));
            gN[s] = fma2(d0, wiN0, fma2(d1, wiN1, binN));
            aN[s] = bhnN;   // b_hh_n seeds the recurrent part (lives inside r*(...))
        }

        const float* hrow = sH + half * 8 * 128;
        #pragma unroll 4
        for (int k = 0; k < 128; k++) {
            const u64* wk = (const u64*)(sW + k * 384);
            u64 wr = wk[c];
            u64 wz = wk[64 + c];
            u64 wn = wk[128 + c];
            #pragma unroll
            for (int s = 0; s < 8; s++) {
                u64 h2 = dup2(hrow[s * 128 + k]);
                aR[s] = fma2(h2, wr, aR[s]);
                aZ[s] = fma2(h2, wz, aZ[s]);
                aN[s] = fma2(h2, wn, aN[s]);
            }
        }

        __syncthreads();   // everyone done reading sH for this step
        #pragma unroll
        for (int s = 0; s < 8; s++) {
            float rx, ry, zx, zy, nx, ny, gx, gy, hx, hy;
            unpack2(aR[s], rx, ry);
            unpack2(aZ[s], zx, zy);
            unpack2(aN[s], nx, ny);
            unpack2(gN[s], gx, gy);
            unpack2(hprev[s], hx, hy);
            rx = sigf(rx); ry = sigf(ry);
            zx = sigf(zx); zy = sigf(zy);
            nx = tanhfast(gx + rx * nx);
            ny = tanhfast(gy + ry * ny);
            hx = (1.0f - zx) * nx + zx * hx;
            hy = (1.0f - zy) * ny + zy * hy;
            hprev[s] = pack2(hx, hy);
            int sg = half * 8 + s;
            float2 hv = make_float2(hx, hy);
            *(float2*)(sH + sg * 128 + j0) = hv;
            *(float2*)(g_hs + ((size_t)(bBase + sg) * T_STEPS + t) * NH + j0) = hv;
        }
        __syncthreads();
    }
}

// ============================================================================
// Kernel 2: MLP head + softmax log-prob. 16 samples/CTA, 128 threads.
// ============================================================================
__global__ __launch_bounds__(128, 2) void head_kernel(
    const float* __restrict__ x, const float* __restrict__ w1,
    const float* __restrict__ b1, const float* __restrict__ w2,
    const float* __restrict__ b2, float* __restrict__ out)
{
    extern __shared__ float sm[];
    float* sW1  = sm;                 // [k=128][j=128] (k-major)
    float* sH   = sW1 + 128 * 128;    // [16][128]
    float* sHid = sH + 16 * 128;      // [16][130] padded
    float* sW2  = sHid + 16 * 130;    // [4][132] padded
    float* sLog = sW2 + 4 * 132;      // [64]

    const int tid = threadIdx.x;
    const int c = tid & 63, half = tid >> 6;
    const int bBase = blockIdx.x * 16;
    const int j0 = 2 * c;

    for (int i = tid; i < 128 * 128; i += 128) {
        int j = i >> 7, k = i & 127;
        sW1[k * 128 + j] = w1[i];
    }
    for (int i = tid; i < 4 * 128; i += 128) {
        int o = i >> 7, k = i & 127;
        sW2[o * 132 + k] = w2[i];
    }
    u64 bias1 = pack2(b1[j0], b1[j0 + 1]);
    float acc = 0.0f;
    __syncthreads();

    for (int t = 0; t < T_STEPS; t++) {
        // stage h_t for 16 samples (coalesced)
        for (int i = tid; i < 16 * 128; i += 128) {
            int s = i >> 7, k = i & 127;
            sH[i] = g_hs[((size_t)(bBase + s) * T_STEPS + t) * NH + k];
        }
        __syncthreads();

        // hid = relu(h @ w1^T + b1)
        u64 a[8];
        #pragma unroll
        for (int s = 0; s < 8; s++) a[s] = bias1;
        #pragma unroll 4
        for (int k = 0; k < 128; k++) {
            u64 w = ((const u64*)(sW1 + k * 128))[c];
            #pragma unroll
            for (int s = 0; s < 8; s++) {
                u64 h2 = dup2(sH[(half * 8 + s) * 128 + k]);
                a[s] = fma2(h2, w, a[s]);
            }
        }
        #pragma unroll
        for (int s = 0; s < 8; s++) {
            float hx, hy;
            unpack2(a[s], hx, hy);
            hx = fmaxf(hx, 0.0f);
            hy = fmaxf(hy, 0.0f);
            *(float2*)(sHid + (half * 8 + s) * 130 + j0) = make_float2(hx, hy);
        }
        __syncthreads();

        // logits: 16 samples x 4 classes on the first 64 threads
        if (tid < 64) {
            int s = tid >> 2, o = tid & 3;
            float d = b2[o];
            #pragma unroll 4
            for (int k = 0; k < 128; k++)
                d += sHid[s * 130 + k] * sW2[o * 132 + k];
            sLog[tid] = d;
        }
        __syncthreads();

        // per-sample log-prob of the true patch
        if (tid < 16) {
            size_t b = (size_t)(bBase + tid) * SEQ_L;
            int i0 = (x[b + 2 * t] != 0.0f) ? 1 : 0;
            int i1 = (x[b + 2 * t + 1] != 0.0f) ? 1 : 0;
            int idx = i0 + 2 * i1;
            float l0 = sLog[tid * 4], l1 = sLog[tid * 4 + 1];
            float l2 = sLog[tid * 4 + 2], l3 = sLog[tid * 4 + 3];
            float m = fmaxf(fmaxf(l0, l1), fmaxf(l2, l3));
            float lse = m + __logf(__expf(l0 - m) + __expf(l1 - m) +
                                   __expf(l2 - m) + __expf(l3 - m));
            acc += sLog[tid * 4 + idx] - lse;
        }
        __syncthreads();
    }
    if (tid < 16) out[bBase + tid] = acc;
}

// smem sizes
#define SMEM1 (128 * 384 * 4 + 16 * 128 * 4 + 32 * 16)          // 205312
#define SMEM2 ((128 * 128 + 16 * 128 + 16 * 130 + 4 * 132 + 64) * 4)  // 84416

extern "C" void kernel_launch(void* const* d_in, const int* in_sizes, int n_in,
                              void* d_out, int out_size) {
    const float* x    = (const float*)d_in[0];
    const float* w_ih = (const float*)d_in[1];
    const float* w_hh = (const float*)d_in[2];
    const float* b_ih = (const float*)d_in[3];
    const float* b_hh = (const float*)d_in[4];
    const float* w1   = (const float*)d_in[5];
    const float* b1   = (const float*)d_in[6];
    const float* w2   = (const float*)d_in[7];
    const float* b2   = (const float*)d_in[8];
    float* out = (float*)d_out;

    cudaFuncSetAttribute(gru_kernel, cudaFuncAttributeMaxDynamicSharedMemorySize, SMEM1);
    cudaFuncSetAttribute(head_kernel, cudaFuncAttributeMaxDynamicSharedMemorySize, SMEM2);

    gru_kernel<<<BATCH / 16, 128, SMEM1>>>(x, w_ih, w_hh, b_ih, b_hh);
    head_kernel<<<BATCH / 16, 128, SMEM2>>>(x, w1, b1, w2, b2, out);
}